// round 9
// baseline (speedup 1.0000x reference)
#include <cuda_runtime.h>
#include <cuda_bf16.h>
#include <math.h>
#include <stdint.h>

// ===========================================================================
// ConvTransBlock via legacy tensor-core path (mma.sync bf16, hi/lo split).
// B=2, H=W=256, C=256 (CD=128 | TD=128), WS=8, NH=4, HD=32.
// R9: 256x128 tile (512 thr), 3-stage cp.async pipeline, 25% less L2 traffic.
// ===========================================================================

#define M_TOK 131072

// ---------------- fp32 buffers ----------------
__device__ float g_y  [131072 * 256];   // conv1 out
__device__ float g_qkv[131072 * 384];
__device__ float g_t  [131072 * 128];   // trans after proj residual

// ---------------- bf16 hi/lo activation buffers ----------------
__device__ __nv_bfloat16 g_xh[131072*256], g_xl[131072*256];
__device__ __nv_bfloat16 g_yh[131072*128], g_yl[131072*128];   // conv half of y
__device__ __nv_bfloat16 g_rh[131072*128], g_rl[131072*128];
__device__ __nv_bfloat16 g_ch[131072*128], g_cl[131072*128];   // cx
__device__ __nv_bfloat16 g_lh[131072*128], g_ll[131072*128];   // ln out
__device__ __nv_bfloat16 g_ah[131072*128], g_al[131072*128];   // attn out
__device__ __nv_bfloat16 g_uh[131072*512], g_ul[131072*512];   // mlp hidden
__device__ __nv_bfloat16 g_th[131072*128], g_tl[131072*128];   // t2

// transposed bf16 weights (hi / lo), K-major rows per n
#define WT_TOTAL 622592
__device__ __align__(256) __nv_bfloat16 g_wth[WT_TOTAL];
__device__ __align__(256) __nv_bfloat16 g_wtl[WT_TOTAL];
#define OFF_C1   0
#define OFF_RW1  65536
#define OFF_RW2  212992
#define OFF_QKV  360448
#define OFF_PW   409600
#define OFF_MW1  425984
#define OFF_MW2  491520
#define OFF_C2   557056

// ---------------- PTX helpers (all sm_80-compatible) ----------------
__device__ __forceinline__ uint32_t smem_u32(const void* p) {
    uint32_t a;
    asm("{ .reg .u64 t; cvta.to.shared.u64 t, %1; cvt.u32.u64 %0, t; }" : "=r"(a) : "l"(p));
    return a;
}
#define CP_ASYNC(dst, src, sz) \
    asm volatile("cp.async.cg.shared.global [%0], [%1], 16, %2;" \
        :: "r"(dst), "l"(src), "r"(sz))
#define CP_COMMIT() asm volatile("cp.async.commit_group;")
#define CP_WAIT(n)  asm volatile("cp.async.wait_group %0;" :: "n"(n))
#define LDM4(r, addr) \
    asm volatile("ldmatrix.sync.aligned.m8n8.x4.shared.b16 {%0,%1,%2,%3}, [%4];" \
        : "=r"((r)[0]), "=r"((r)[1]), "=r"((r)[2]), "=r"((r)[3]) : "r"(addr))
#define MMA(d, a, b0, b1) \
    asm volatile("mma.sync.aligned.m16n8k16.row.col.f32.bf16.bf16.f32 " \
        "{%0,%1,%2,%3}, {%4,%5,%6,%7}, {%8,%9}, {%0,%1,%2,%3};" \
        : "+f"((d)[0]), "+f"((d)[1]), "+f"((d)[2]), "+f"((d)[3]) \
        : "r"((a)[0]), "r"((a)[1]), "r"((a)[2]), "r"((a)[3]), "r"(b0), "r"(b1))

__device__ __forceinline__ uint32_t pack_bf2(float a, float b) {
    __nv_bfloat16 ha = __float2bfloat16(a), hb = __float2bfloat16(b);
    return ((uint32_t)__bfloat16_as_ushort(hb) << 16) | (uint32_t)__bfloat16_as_ushort(ha);
}

// ---------------- weight prep: W[k][n] -> Wt[n][k] bf16 hi/lo ----------------
struct PrepArgs { const float* src[8]; int K[8], N[8], off[8]; };
__global__ void __launch_bounds__(256) prep_k(PrepArgs a,
    __nv_bfloat16* __restrict__ dh, __nv_bfloat16* __restrict__ dl)
{
    int w = blockIdx.y;
    int K = a.K[w], N = a.N[w];
    int idx = blockIdx.x * 256 + threadIdx.x;
    if (idx >= K * N) return;
    int n = idx / K, k = idx - n * K;
    float v = a.src[w][(size_t)k * N + n];
    __nv_bfloat16 h = __float2bfloat16(v);
    dh[a.off[w] + idx] = h;
    dl[a.off[w] + idx] = __float2bfloat16(v - __bfloat162float(h));
}

// ---------------- fp32 -> bf16 hi/lo converter (for x) ----------------
__global__ void __launch_bounds__(256) cvt_k(const float* __restrict__ in,
    __nv_bfloat16* __restrict__ oh, __nv_bfloat16* __restrict__ ol, int n4)
{
    int i = blockIdx.x * 256 + threadIdx.x;
    if (i >= n4) return;
    float4 v = ((const float4*)in)[i];
    float h0 = __bfloat162float(__float2bfloat16(v.x));
    float h1 = __bfloat162float(__float2bfloat16(v.y));
    float h2 = __bfloat162float(__float2bfloat16(v.z));
    float h3 = __bfloat162float(__float2bfloat16(v.w));
    uint2 H = make_uint2(pack_bf2(v.x, v.y), pack_bf2(v.z, v.w));
    uint2 L = make_uint2(pack_bf2(v.x - h0, v.y - h1), pack_bf2(v.z - h2, v.w - h3));
    ((uint2*)oh)[i] = H;
    ((uint2*)ol)[i] = L;
}

// ---------------- unified tensor-core GEMM / implicit-GEMM conv ----------------
// Block tile: 256(M) x 128(N), 512 threads (16 warps, warp = m64 x n32).
// MODE: 0 gemm, 1 concat(A0bf,A1bf) along K, 2 conv3x3 (A = [M,128] bf16, halo)
// EPI:  0 bias; 1 bias+gelu; 2 bias+res; 3 bias+lrelu; 4 bias+lrelu+2*res
// WF:   write fp32 out;  WBF: write bf16 hi/lo out (cols < ldob)
#define RS 80                       // smem row stride bytes (32 bf16 + pad)
// stage layout: AH@0 (256*80) | AL@20480 | BH@40960 (128*80) | BL@51200
#define STAGE_SZ 61440
#define SMEM_TOTAL (3 * STAGE_SZ)   // 184320 bytes, 3-stage pipeline

template<int MODE, int EPI, int WF, int WBF>
__global__ void __launch_bounds__(512, 1) mm_k(
    const __nv_bfloat16* __restrict__ AH0, const __nv_bfloat16* __restrict__ AL0,
    const __nv_bfloat16* __restrict__ AH1, const __nv_bfloat16* __restrict__ AL1,
    int ldA,
    const __nv_bfloat16* __restrict__ WH, const __nv_bfloat16* __restrict__ WL,
    int Kw,
    const float* __restrict__ bias,
    const float* __restrict__ res, int ldRes,
    float* __restrict__ out, int ldo,
    __nv_bfloat16* __restrict__ obH, __nv_bfloat16* __restrict__ obL, int ldob)
{
    extern __shared__ char sm[];
    const uint32_t sb = smem_u32(sm);
    const int tid = threadIdx.x;
    const int wid = tid >> 5;
    const int lane = tid & 31;
    const int nc = Kw >> 5;

    int m0 = 0, n0 = 0, bB = 0, gh0 = 0, gw0 = 0;
    if (MODE == 2) {
        bB  = blockIdx.x >> 8;
        gh0 = ((blockIdx.x >> 4) & 15) * 16;
        gw0 = (blockIdx.x & 15) * 16;
    } else {
        m0 = blockIdx.x * 256;
        n0 = blockIdx.y * 128;
    }

    // loader mapping:
    //   A: 256 rows, 2 threads/row, each a 32B half (2x16B) per matrix
    //   B: 128 rows, 4 threads/row, each a 16B quarter per matrix
    const int ar  = tid >> 1;           // 0..255
    const int ahf = (tid & 1) * 32;     // byte offset within 64B row
    const int br  = tid >> 2;           // 0..127
    const int bq  = (tid & 3) * 16;
    int lph = 0, lpw = 0;
    if (MODE == 2) { lph = gh0 + (ar >> 4); lpw = gw0 + (ar & 15); }

    auto issue_chunk = [&](int cc, int buf) {
        const uint32_t base = sb + (uint32_t)buf * STAGE_SZ;
        const int kin = cc * 32;
        // ---- A ----
        const __nv_bfloat16 *ah, *al;
        uint32_t asz = 16;
        if (MODE == 0) {
            ah = AH0 + (size_t)(m0 + ar) * ldA + kin;
            al = AL0 + (size_t)(m0 + ar) * ldA + kin;
        } else if (MODE == 1) {
            if (kin < 128) {
                ah = AH0 + (size_t)(m0 + ar) * 128 + kin;
                al = AL0 + (size_t)(m0 + ar) * 128 + kin;
            } else {
                ah = AH1 + (size_t)(m0 + ar) * 128 + (kin - 128);
                al = AL1 + (size_t)(m0 + ar) * 128 + (kin - 128);
            }
        } else {
            const int tap = cc >> 2, kk = (cc & 3) * 32;
            const int ih = lph + tap / 3 - 1, iw = lpw + tap % 3 - 1;
            const bool ok = ((unsigned)ih < 256u) && ((unsigned)iw < 256u);
            const size_t pix = ok ? (size_t)((bB * 256 + ih) * 256 + iw) : 0;
            ah = AH0 + pix * 128 + kk;
            al = AL0 + pix * 128 + kk;
            asz = ok ? 16u : 0u;
        }
        const uint32_t da = base + (uint32_t)ar * RS + ahf;
        CP_ASYNC(da,              (const char*)ah + ahf,      asz);
        CP_ASYNC(da + 16,         (const char*)ah + ahf + 16, asz);
        CP_ASYNC(da + 20480,      (const char*)al + ahf,      asz);
        CP_ASYNC(da + 20480 + 16, (const char*)al + ahf + 16, asz);
        // ---- B (weights, K-major rows) ----
        const __nv_bfloat16* bh = WH + (size_t)(n0 + br) * Kw + kin;
        const __nv_bfloat16* bl = WL + (size_t)(n0 + br) * Kw + kin;
        const uint32_t db = base + 40960 + (uint32_t)br * RS + bq;
        CP_ASYNC(db,         (const char*)bh + bq, 16);
        CP_ASYNC(db + 10240, (const char*)bl + bq, 16);
    };

    // warp tiling: warp_m in {0..3} (64 rows), warp_n in {0,1,2,3}>>2... wn {0..3}*32
    const int wm = (wid & 3) * 64;
    const int wn = (wid >> 2) * 32;
    const uint32_t a_lo = (uint32_t)(lane & 15) * RS + (uint32_t)(lane >> 4) * 16;
    const uint32_t b_lo = (uint32_t)((lane & 7) + ((lane >> 4) << 3)) * RS
                        + (uint32_t)((lane >> 3) & 1) * 16;

    float acc[4][4][4] = {};

    // 3-stage pipeline: 2 chunks in flight, wait_group 1
    issue_chunk(0, 0); CP_COMMIT();
    issue_chunk(1, 1); CP_COMMIT();

    int cb = 0;   // buffer of chunk c
    for (int c = 0; c < nc; c++) {
        CP_WAIT(1);          // chunk c complete (c+1 may still be in flight)
        __syncthreads();     // all warps done reading buf (c+2)%3 (compute c-1)
        if (c + 2 < nc) issue_chunk(c + 2, cb == 0 ? 2 : cb - 1);  // (cb+2)%3
        CP_COMMIT();         // always commit (possibly empty) so tail drains

        const uint32_t base = sb + (uint32_t)cb * STAGE_SZ;
        #pragma unroll
        for (int ks = 0; ks < 2; ks++) {
            // a-register reuse: aR holds aH for s0/s1, then aL for s2.
            uint32_t aR[4][4], bH[2][4], bL[2][4];
            #pragma unroll
            for (int bg = 0; bg < 2; bg++) {
                const uint32_t bd = base + 40960 + (uint32_t)(wn + bg * 16) * RS + ks * 32 + b_lo;
                LDM4(bH[bg], bd);
                LDM4(bL[bg], bd + 10240);
            }
            #pragma unroll
            for (int mi = 0; mi < 4; mi++) {
                const uint32_t ad = base + (uint32_t)(wm + mi * 16) * RS + ks * 32 + a_lo;
                LDM4(aR[mi], ad);
            }
            // s0: aH * bH
            #pragma unroll
            for (int mi = 0; mi < 4; mi++)
                #pragma unroll
                for (int nj = 0; nj < 4; nj++) {
                    const uint32_t* bf = &bH[nj >> 1][(nj & 1) * 2];
                    MMA(acc[mi][nj], aR[mi], bf[0], bf[1]);
                }
            // s1: aH * bL
            #pragma unroll
            for (int mi = 0; mi < 4; mi++)
                #pragma unroll
                for (int nj = 0; nj < 4; nj++) {
                    const uint32_t* bf = &bL[nj >> 1][(nj & 1) * 2];
                    MMA(acc[mi][nj], aR[mi], bf[0], bf[1]);
                }
            // reload aR with aL
            #pragma unroll
            for (int mi = 0; mi < 4; mi++) {
                const uint32_t ad = base + (uint32_t)(wm + mi * 16) * RS + ks * 32 + a_lo;
                LDM4(aR[mi], ad + 20480);
            }
            // s2: aL * bH
            #pragma unroll
            for (int mi = 0; mi < 4; mi++)
                #pragma unroll
                for (int nj = 0; nj < 4; nj++) {
                    const uint32_t* bf = &bH[nj >> 1][(nj & 1) * 2];
                    MMA(acc[mi][nj], aR[mi], bf[0], bf[1]);
                }
        }
        cb = (cb == 2) ? 0 : cb + 1;
    }

    // ---- epilogue ----
    #pragma unroll
    for (int mi = 0; mi < 4; mi++) {
        #pragma unroll
        for (int h2 = 0; h2 < 2; h2++) {
            const int r = wm + mi * 16 + (lane >> 2) + h2 * 8;
            size_t orow;
            if (MODE == 2)
                orow = (size_t)((bB * 256 + gh0 + (r >> 4)) * 256 + gw0 + (r & 15));
            else
                orow = (size_t)(m0 + r);
            #pragma unroll
            for (int nj = 0; nj < 4; nj++) {
                const int n = n0 + wn + nj * 8 + (lane & 3) * 2;
                float v0 = acc[mi][nj][h2 * 2 + 0] + __ldg(&bias[n]);
                float v1 = acc[mi][nj][h2 * 2 + 1] + __ldg(&bias[n + 1]);
                if (EPI == 1) {
                    v0 = 0.5f * v0 * (1.0f + erff(v0 * 0.7071067811865476f));
                    v1 = 0.5f * v1 * (1.0f + erff(v1 * 0.7071067811865476f));
                }
                if (EPI == 3 || EPI == 4) {
                    v0 = v0 >= 0.f ? v0 : 0.01f * v0;
                    v1 = v1 >= 0.f ? v1 : 0.01f * v1;
                }
                if (EPI == 2) {
                    const float2 rv = *(const float2*)(res + orow * ldRes + n);
                    v0 += rv.x; v1 += rv.y;
                }
                if (EPI == 4) {
                    const float2 rv = *(const float2*)(res + orow * ldRes + n);
                    v0 += 2.f * rv.x; v1 += 2.f * rv.y;
                }
                if (WF)
                    *(float2*)(out + orow * ldo + n) = make_float2(v0, v1);
                if (WBF && n < ldob) {
                    float h0 = __bfloat162float(__float2bfloat16(v0));
                    float h1 = __bfloat162float(__float2bfloat16(v1));
                    *(uint32_t*)(obH + orow * ldob + n) = pack_bf2(v0, v1);
                    *(uint32_t*)(obL + orow * ldob + n) = pack_bf2(v0 - h0, v1 - h1);
                }
            }
        }
    }
}

// ---------------- LayerNorm (fp32 in, bf16 hi/lo out) ----------------
__global__ void __launch_bounds__(256) ln_k(
    const float* __restrict__ in, int stride,
    const float* __restrict__ g, const float* __restrict__ bta,
    __nv_bfloat16* __restrict__ oh, __nv_bfloat16* __restrict__ ol)
{
    const int token = blockIdx.x * 8 + (threadIdx.x >> 5);
    const int lane = threadIdx.x & 31;
    const float* p = in + (size_t)token * stride;
    float4 v = *(const float4*)(p + lane * 4);
    float s  = v.x + v.y + v.z + v.w;
    float sq = v.x * v.x + v.y * v.y + v.z * v.z + v.w * v.w;
    #pragma unroll
    for (int o = 16; o; o >>= 1) {
        s  += __shfl_xor_sync(0xffffffffu, s,  o);
        sq += __shfl_xor_sync(0xffffffffu, sq, o);
    }
    const float mu  = s * (1.0f / 128.0f);
    const float var = sq * (1.0f / 128.0f) - mu * mu;
    const float rs  = rsqrtf(var + 1e-5f);
    float4 gv = *(const float4*)(g + lane * 4);
    float4 bv = *(const float4*)(bta + lane * 4);
    float o0 = (v.x - mu) * rs * gv.x + bv.x;
    float o1 = (v.y - mu) * rs * gv.y + bv.y;
    float o2 = (v.z - mu) * rs * gv.z + bv.z;
    float o3 = (v.w - mu) * rs * gv.w + bv.w;
    float h0 = __bfloat162float(__float2bfloat16(o0));
    float h1 = __bfloat162float(__float2bfloat16(o1));
    float h2 = __bfloat162float(__float2bfloat16(o2));
    float h3 = __bfloat162float(__float2bfloat16(o3));
    const size_t off = (size_t)token * 128 + lane * 4;
    *(uint2*)(oh + off) = make_uint2(pack_bf2(o0, o1), pack_bf2(o2, o3));
    *(uint2*)(ol + off) = make_uint2(pack_bf2(o0 - h0, o1 - h1), pack_bf2(o2 - h2, o3 - h3));
}

// ---------------- windowed attention (fp32; bf16 hi/lo out) ----------------
__global__ void __launch_bounds__(256) attn_k(
    const float* __restrict__ qkv, const float* __restrict__ rpb,
    __nv_bfloat16* __restrict__ oh, __nv_bfloat16* __restrict__ ol)
{
    __shared__ float qs[64][32];
    __shared__ float ks[64][33];
    __shared__ float vs[64][33];
    __shared__ float Ps[64][65];
    __shared__ int pixS[64];
    __shared__ int ridS[64];

    const int tid = threadIdx.x;
    const int head = blockIdx.x & 3;
    const int w = (blockIdx.x >> 2) & 1023;
    const int b = blockIdx.x >> 12;
    const int wi = w >> 5, wj = w & 31;

    if (tid < 64) {
        const int ti = tid >> 3, tj = tid & 7;
        const int hh = wi * 8 + ti, ww = wj * 8 + tj;
        pixS[tid] = (b * 256 + ((hh + 4) & 255)) * 256 + ((ww + 4) & 255);
        const int rh = hh < 248 ? 0 : (hh < 252 ? 1 : 2);
        const int rw = ww < 248 ? 0 : (ww < 252 ? 1 : 2);
        ridS[tid] = rh * 3 + rw;
    }
    __syncthreads();

    const int ho = head * 32;
    for (int idx = tid; idx < 2048; idx += 256) {
        const int t = idx >> 5, d = idx & 31;
        const size_t base = (size_t)pixS[t] * 384 + ho + d;
        qs[t][d] = qkv[base];
        ks[t][d] = qkv[base + 128];
        vs[t][d] = qkv[base + 256];
    }
    __syncthreads();

    const int warp = tid >> 5, lane = tid & 31;
    #pragma unroll
    for (int rr = 0; rr < 8; rr++) {
        const int r = warp * 8 + rr;
        float s0 = 0.f, s1 = 0.f;
        #pragma unroll
        for (int d = 0; d < 32; d++) {
            const float qv = qs[r][d];
            s0 += qv * ks[lane][d];
            s1 += qv * ks[lane + 32][d];
        }
        const int ri = r >> 3, rj = r & 7;
        const int rid_r = ridS[r];
        {
            const int c = lane;
            const int rel = (ri - (c >> 3) + 7) * 15 + (rj - (c & 7) + 7);
            s0 = s0 * 0.17677669529663687f + rpb[rel * 4 + head];
            if (rid_r != ridS[c]) s0 -= 1e9f;
        }
        {
            const int c = lane + 32;
            const int rel = (ri - (c >> 3) + 7) * 15 + (rj - (c & 7) + 7);
            s1 = s1 * 0.17677669529663687f + rpb[rel * 4 + head];
            if (rid_r != ridS[c]) s1 -= 1e9f;
        }
        float mx = fmaxf(s0, s1);
        #pragma unroll
        for (int o = 16; o; o >>= 1) mx = fmaxf(mx, __shfl_xor_sync(0xffffffffu, mx, o));
        float e0 = expf(s0 - mx), e1 = expf(s1 - mx);
        float sm = e0 + e1;
        #pragma unroll
        for (int o = 16; o; o >>= 1) sm += __shfl_xor_sync(0xffffffffu, sm, o);
        const float inv = 1.0f / sm;
        Ps[r][lane] = e0 * inv;
        Ps[r][lane + 32] = e1 * inv;
    }
    __syncthreads();

    const int i = tid >> 2, d0 = (tid & 3) * 8;
    float acc[8] = {};
    #pragma unroll
    for (int j = 0; j < 64; j++) {
        const float p = Ps[i][j];
        #pragma unroll
        for (int dd = 0; dd < 8; dd++) acc[dd] += p * vs[j][d0 + dd];
    }
    const size_t ob = (size_t)pixS[i] * 128 + ho + d0;
    #pragma unroll
    for (int dd = 0; dd < 8; dd += 2) {
        float h0 = __bfloat162float(__float2bfloat16(acc[dd]));
        float h1 = __bfloat162float(__float2bfloat16(acc[dd + 1]));
        *(uint32_t*)(oh + ob + dd) = pack_bf2(acc[dd], acc[dd + 1]);
        *(uint32_t*)(ol + ob + dd) = pack_bf2(acc[dd] - h0, acc[dd + 1] - h1);
    }
}

// ===========================================================================
extern "C" void kernel_launch(void* const* d_in, const int* in_sizes, int n_in,
                              void* d_out, int out_size)
{
    const float* x    = (const float*)d_in[0];
    const float* c1w  = (const float*)d_in[1];
    const float* c1b  = (const float*)d_in[2];
    const float* rw1  = (const float*)d_in[3];
    const float* rb1  = (const float*)d_in[4];
    const float* rw2  = (const float*)d_in[5];
    const float* rb2  = (const float*)d_in[6];
    const float* ln1g = (const float*)d_in[7];
    const float* ln1b = (const float*)d_in[8];
    const float* qkvw = (const float*)d_in[9];
    const float* qkvb = (const float*)d_in[10];
    const float* rpb  = (const float*)d_in[11];
    const float* pw   = (const float*)d_in[12];
    const float* pb   = (const float*)d_in[13];
    const float* ln2g = (const float*)d_in[14];
    const float* ln2b = (const float*)d_in[15];
    const float* mw1  = (const float*)d_in[16];
    const float* mb1  = (const float*)d_in[17];
    const float* mw2  = (const float*)d_in[18];
    const float* mb2  = (const float*)d_in[19];
    const float* c2w  = (const float*)d_in[20];
    const float* c2b  = (const float*)d_in[21];
    float* out = (float*)d_out;

    float *y, *qkv, *t;
    __nv_bfloat16 *xh,*xl,*yh,*yl,*rh,*rl,*ch,*cl,*lh,*ll,*ah,*al,*uh,*ul,*th,*tl,*wth,*wtl;
    cudaGetSymbolAddress((void**)&y,   g_y);
    cudaGetSymbolAddress((void**)&qkv, g_qkv);
    cudaGetSymbolAddress((void**)&t,   g_t);
    cudaGetSymbolAddress((void**)&xh, g_xh); cudaGetSymbolAddress((void**)&xl, g_xl);
    cudaGetSymbolAddress((void**)&yh, g_yh); cudaGetSymbolAddress((void**)&yl, g_yl);
    cudaGetSymbolAddress((void**)&rh, g_rh); cudaGetSymbolAddress((void**)&rl, g_rl);
    cudaGetSymbolAddress((void**)&ch, g_ch); cudaGetSymbolAddress((void**)&cl, g_cl);
    cudaGetSymbolAddress((void**)&lh, g_lh); cudaGetSymbolAddress((void**)&ll, g_ll);
    cudaGetSymbolAddress((void**)&ah, g_ah); cudaGetSymbolAddress((void**)&al, g_al);
    cudaGetSymbolAddress((void**)&uh, g_uh); cudaGetSymbolAddress((void**)&ul, g_ul);
    cudaGetSymbolAddress((void**)&th, g_th); cudaGetSymbolAddress((void**)&tl, g_tl);
    cudaGetSymbolAddress((void**)&wth, g_wth); cudaGetSymbolAddress((void**)&wtl, g_wtl);

    // one-time objects (same work every call; creation only happens once,
    // before the first graph capture)
    static cudaStream_t s2 = nullptr;
    static cudaEvent_t evFork = nullptr, evJoin = nullptr;
    if (s2 == nullptr) {
        cudaStreamCreateWithFlags(&s2, cudaStreamNonBlocking);
        cudaEventCreateWithFlags(&evFork, cudaEventDisableTiming);
        cudaEventCreateWithFlags(&evJoin, cudaEventDisableTiming);
        cudaFuncSetAttribute(mm_k<0,0,1,1>, cudaFuncAttributeMaxDynamicSharedMemorySize, SMEM_TOTAL);
        cudaFuncSetAttribute(mm_k<2,3,0,1>, cudaFuncAttributeMaxDynamicSharedMemorySize, SMEM_TOTAL);
        cudaFuncSetAttribute(mm_k<2,4,0,1>, cudaFuncAttributeMaxDynamicSharedMemorySize, SMEM_TOTAL);
        cudaFuncSetAttribute(mm_k<0,0,1,0>, cudaFuncAttributeMaxDynamicSharedMemorySize, SMEM_TOTAL);
        cudaFuncSetAttribute(mm_k<0,2,1,0>, cudaFuncAttributeMaxDynamicSharedMemorySize, SMEM_TOTAL);
        cudaFuncSetAttribute(mm_k<0,1,0,1>, cudaFuncAttributeMaxDynamicSharedMemorySize, SMEM_TOTAL);
        cudaFuncSetAttribute(mm_k<0,2,0,1>, cudaFuncAttributeMaxDynamicSharedMemorySize, SMEM_TOTAL);
        cudaFuncSetAttribute(mm_k<1,2,1,0>, cudaFuncAttributeMaxDynamicSharedMemorySize, SMEM_TOTAL);
    }

    // 0a. weight prep
    PrepArgs pa;
    pa.src[0]=c1w; pa.K[0]=256;  pa.N[0]=256; pa.off[0]=OFF_C1;
    pa.src[1]=rw1; pa.K[1]=1152; pa.N[1]=128; pa.off[1]=OFF_RW1;
    pa.src[2]=rw2; pa.K[2]=1152; pa.N[2]=128; pa.off[2]=OFF_RW2;
    pa.src[3]=qkvw;pa.K[3]=128;  pa.N[3]=384; pa.off[3]=OFF_QKV;
    pa.src[4]=pw;  pa.K[4]=128;  pa.N[4]=128; pa.off[4]=OFF_PW;
    pa.src[5]=mw1; pa.K[5]=128;  pa.N[5]=512; pa.off[5]=OFF_MW1;
    pa.src[6]=mw2; pa.K[6]=512;  pa.N[6]=128; pa.off[6]=OFF_MW2;
    pa.src[7]=c2w; pa.K[7]=256;  pa.N[7]=256; pa.off[7]=OFF_C2;
    prep_k<<<dim3(576, 8), 256>>>(pa, wth, wtl);
    // 0b. convert x
    cvt_k<<<32768, 256>>>(x, xh, xl, M_TOK * 64);

    const int M = M_TOK;
    dim3 thr(512);
    // 1. conv1x1 #1: y(fp32 [M,256]) + ybf(cols 0-127)
    mm_k<0,0,1,1><<<dim3(M/256, 2), thr, SMEM_TOTAL>>>(
        xh, xl, nullptr, nullptr, 256, wth+OFF_C1, wtl+OFF_C1, 256,
        c1b, nullptr, 0, y, 256, yh, yl, 128);

    // ---- fork: conv branch on s2, transformer branch on capture stream ----
    cudaEventRecord(evFork, 0);
    cudaStreamWaitEvent(s2, evFork, 0);

    // conv branch (s2)
    // 2. conv3x3 #1 + lrelu -> rbf
    mm_k<2,3,0,1><<<512, thr, SMEM_TOTAL, s2>>>(
        yh, yl, nullptr, nullptr, 128, wth+OFF_RW1, wtl+OFF_RW1, 1152,
        rb1, nullptr, 0, nullptr, 0, rh, rl, 128);
    // 3. conv3x3 #2 + lrelu + 2*conv_x -> cxbf
    mm_k<2,4,0,1><<<512, thr, SMEM_TOTAL, s2>>>(
        rh, rl, nullptr, nullptr, 128, wth+OFF_RW2, wtl+OFF_RW2, 1152,
        rb2, y, 256, nullptr, 0, ch, cl, 128);

    // transformer branch (capture stream)
    // 4. LN1 on trans_x -> lnbf
    ln_k<<<M/8, 256>>>(y + 128, 256, ln1g, ln1b, lh, ll);
    // 5. qkv (fp32)
    mm_k<0,0,1,0><<<dim3(M/256, 3), thr, SMEM_TOTAL>>>(
        lh, ll, nullptr, nullptr, 128, wth+OFF_QKV, wtl+OFF_QKV, 128,
        qkvb, nullptr, 0, qkv, 384, nullptr, nullptr, 0);
    // 6. attention -> attbf
    attn_k<<<8192, 256>>>(qkv, rpb, ah, al);
    // 7. proj + residual(trans_x) -> t (fp32)
    mm_k<0,2,1,0><<<dim3(M/256, 1), thr, SMEM_TOTAL>>>(
        ah, al, nullptr, nullptr, 128, wth+OFF_PW, wtl+OFF_PW, 128,
        pb, y + 128, 256, t, 128, nullptr, nullptr, 0);
    // 8. LN2 -> lnbf
    ln_k<<<M/8, 256>>>(t, 128, ln2g, ln2b, lh, ll);
    // 9. mlp1 + gelu -> ubf
    mm_k<0,1,0,1><<<dim3(M/256, 4), thr, SMEM_TOTAL>>>(
        lh, ll, nullptr, nullptr, 128, wth+OFF_MW1, wtl+OFF_MW1, 128,
        mb1, nullptr, 0, nullptr, 0, uh, ul, 512);
    // 10. mlp2 + residual(t) -> t2bf
    mm_k<0,2,0,1><<<dim3(M/256, 1), thr, SMEM_TOTAL>>>(
        uh, ul, nullptr, nullptr, 512, wth+OFF_MW2, wtl+OFF_MW2, 512,
        mb2, t, 128, nullptr, 0, th, tl, 128);

    // ---- join ----
    cudaEventRecord(evJoin, s2);
    cudaStreamWaitEvent(0, evJoin, 0);

    // 11. conv1x1 #2 on concat(cx,t2) + x -> out
    mm_k<1,2,1,0><<<dim3(M/256, 2), thr, SMEM_TOTAL>>>(
        ch, cl, th, tl, 0, wth+OFF_C2, wtl+OFF_C2, 256,
        c2b, x, 256, out, 256, nullptr, nullptr, 0);
}

// round 11
// speedup vs baseline: 1.7557x; 1.7557x over previous
#include <cuda_runtime.h>
#include <cuda_fp16.h>
#include <math.h>
#include <stdint.h>

// ===========================================================================
// ConvTransBlock via legacy tensor-core path (mma.sync fp16 single-product).
// B=2, H=W=256, C=256 (CD=128 | TD=128), WS=8, NH=4, HD=32.
// R10: R8 tile shape (128x128, 256thr, 2 CTA/SM) + fp16 1-product GEMMs
//      (3x fewer MMAs) + 4-stage cp.async pipeline.
// ===========================================================================

#define M_TOK 131072

// ---------------- fp32 buffers ----------------
__device__ float g_y  [131072 * 256];   // conv1 out
__device__ float g_qkv[131072 * 384];
__device__ float g_t  [131072 * 128];   // trans after proj residual

// ---------------- fp16 activation buffers ----------------
__device__ __half g_x16[131072*256];
__device__ __half g_y16[131072*128];   // conv half of y
__device__ __half g_r16[131072*128];
__device__ __half g_c16[131072*128];   // cx
__device__ __half g_l16[131072*128];   // ln out
__device__ __half g_a16[131072*128];   // attn out
__device__ __half g_u16[131072*512];   // mlp hidden
__device__ __half g_t16[131072*128];   // t2

// transposed fp16 weights, K-major rows per n
#define WT_TOTAL 622592
__device__ __align__(256) __half g_wt[WT_TOTAL];
#define OFF_C1   0
#define OFF_RW1  65536
#define OFF_RW2  212992
#define OFF_QKV  360448
#define OFF_PW   409600
#define OFF_MW1  425984
#define OFF_MW2  491520
#define OFF_C2   557056

// ---------------- PTX helpers (all sm_80-compatible) ----------------
__device__ __forceinline__ uint32_t smem_u32(const void* p) {
    uint32_t a;
    asm("{ .reg .u64 t; cvta.to.shared.u64 t, %1; cvt.u32.u64 %0, t; }" : "=r"(a) : "l"(p));
    return a;
}
#define CP_ASYNC(dst, src, sz) \
    asm volatile("cp.async.cg.shared.global [%0], [%1], 16, %2;" \
        :: "r"(dst), "l"(src), "r"(sz))
#define CP_COMMIT() asm volatile("cp.async.commit_group;")
#define CP_WAIT(n)  asm volatile("cp.async.wait_group %0;" :: "n"(n))
#define LDM4(r, addr) \
    asm volatile("ldmatrix.sync.aligned.m8n8.x4.shared.b16 {%0,%1,%2,%3}, [%4];" \
        : "=r"((r)[0]), "=r"((r)[1]), "=r"((r)[2]), "=r"((r)[3]) : "r"(addr))
#define MMA16(d, a, b0, b1) \
    asm volatile("mma.sync.aligned.m16n8k16.row.col.f32.f16.f16.f32 " \
        "{%0,%1,%2,%3}, {%4,%5,%6,%7}, {%8,%9}, {%0,%1,%2,%3};" \
        : "+f"((d)[0]), "+f"((d)[1]), "+f"((d)[2]), "+f"((d)[3]) \
        : "r"((a)[0]), "r"((a)[1]), "r"((a)[2]), "r"((a)[3]), "r"(b0), "r"(b1))

__device__ __forceinline__ uint32_t pack_h2(float a, float b) {
    __half ha = __float2half_rn(a), hb = __float2half_rn(b);
    return ((uint32_t)__half_as_ushort(hb) << 16) | (uint32_t)__half_as_ushort(ha);
}

// ---------------- weight prep: W[k][n] -> Wt[n][k] fp16 ----------------
struct PrepArgs { const float* src[8]; int K[8], N[8], off[8]; };
__global__ void __launch_bounds__(256) prep_k(PrepArgs a, __half* __restrict__ d)
{
    int w = blockIdx.y;
    int K = a.K[w], N = a.N[w];
    int idx = blockIdx.x * 256 + threadIdx.x;
    if (idx >= K * N) return;
    int n = idx / K, k = idx - n * K;
    d[a.off[w] + idx] = __float2half_rn(a.src[w][(size_t)k * N + n]);
}

// ---------------- fp32 -> fp16 converter (for x) ----------------
__global__ void __launch_bounds__(256) cvt_k(const float* __restrict__ in,
    __half* __restrict__ o16, int n4)
{
    int i = blockIdx.x * 256 + threadIdx.x;
    if (i >= n4) return;
    float4 v = ((const float4*)in)[i];
    ((uint2*)o16)[i] = make_uint2(pack_h2(v.x, v.y), pack_h2(v.z, v.w));
}

// ---------------- unified tensor-core GEMM / implicit-GEMM conv ----------------
// Block tile 128x128, 256 threads (8 warps, warp = m64 x n32), 2 CTAs/SM.
// MODE: 0 gemm, 1 concat(A0,A1) along K, 2 conv3x3 (A = [M,128] fp16, halo)
// EPI:  0 bias; 1 bias+gelu; 2 bias+res; 3 bias+lrelu; 4 bias+lrelu+2*res
// WF:   write fp32 out;  WBF: write fp16 out (cols < ldob)
#define RS 80                       // smem row stride bytes (32 fp16 + pad)
#define STAGE_SZ 20480              // A@0 (128*80) | B@10240 (128*80)
#define NSTAGE 4
#define SMEM_TOTAL (NSTAGE * STAGE_SZ)   // 81920 B/CTA, 2 CTAs = 160 KB/SM

template<int MODE, int EPI, int WF, int WBF>
__global__ void __launch_bounds__(256, 2) mm_k(
    const __half* __restrict__ A0, const __half* __restrict__ A1, int ldA,
    const __half* __restrict__ WH, int Kw,
    const float* __restrict__ bias,
    const float* __restrict__ res, int ldRes,
    float* __restrict__ out, int ldo,
    __half* __restrict__ ob, int ldob)
{
    extern __shared__ char sm[];
    const uint32_t sb = smem_u32(sm);
    const int tid = threadIdx.x;
    const int wid = tid >> 5;
    const int lane = tid & 31;
    const int nc = Kw >> 5;

    int m0 = 0, n0 = 0, bB = 0, gh0 = 0, gw0 = 0;
    if (MODE == 2) {
        bB  = blockIdx.x >> 9;
        gh0 = ((blockIdx.x >> 4) & 31) * 8;
        gw0 = (blockIdx.x & 15) * 16;
    } else {
        m0 = blockIdx.x * 128;
        n0 = blockIdx.y * 128;
    }

    // loader mapping: 2 threads per row, each covers a 32B k-half (2x16B)
    const int lr = tid >> 1;
    const int lh = tid & 1;
    int lph = 0, lpw = 0;
    if (MODE == 2) { lph = gh0 + (lr >> 4); lpw = gw0 + (lr & 15); }

    auto issue_chunk = [&](int cc, int buf) {
        const uint32_t base = sb + (uint32_t)buf * STAGE_SZ;
        const int kin = cc * 32;
        // ---- A ----
        const __half* ah;
        uint32_t asz = 16;
        if (MODE == 0) {
            ah = A0 + (size_t)(m0 + lr) * ldA + kin;
        } else if (MODE == 1) {
            ah = (kin < 128) ? A0 + (size_t)(m0 + lr) * 128 + kin
                             : A1 + (size_t)(m0 + lr) * 128 + (kin - 128);
        } else {
            const int tap = cc >> 2, kk = (cc & 3) * 32;
            const int ih = lph + tap / 3 - 1, iw = lpw + tap % 3 - 1;
            const bool ok = ((unsigned)ih < 256u) && ((unsigned)iw < 256u);
            const size_t pix = ok ? (size_t)((bB * 256 + ih) * 256 + iw) : 0;
            ah = A0 + pix * 128 + kk;
            asz = ok ? 16u : 0u;
        }
        const uint32_t da = base + (uint32_t)lr * RS + lh * 32;
        CP_ASYNC(da,      (const char*)ah + lh * 32,      asz);
        CP_ASYNC(da + 16, (const char*)ah + lh * 32 + 16, asz);
        // ---- B (weights, K-major rows) ----
        const __half* bh = WH + (size_t)(n0 + lr) * Kw + kin;
        const uint32_t db = base + 10240 + (uint32_t)lr * RS + lh * 32;
        CP_ASYNC(db,      (const char*)bh + lh * 32,      16);
        CP_ASYNC(db + 16, (const char*)bh + lh * 32 + 16, 16);
    };

    // warp tiling: warp_m in {0,1} (64 rows), warp_n in {0..3} (32 cols)
    const int wm = (wid & 1) * 64;
    const int wn = (wid >> 1) * 32;
    const uint32_t a_lo = (uint32_t)(lane & 15) * RS + (uint32_t)(lane >> 4) * 16;
    const uint32_t b_lo = (uint32_t)((lane & 7) + ((lane >> 4) << 3)) * RS
                        + (uint32_t)((lane >> 3) & 1) * 16;

    float acc[4][4][4] = {};

    // 4-stage pipeline: 3 chunks in flight, wait_group 2
    issue_chunk(0, 0); CP_COMMIT();
    if (nc > 1) issue_chunk(1, 1);
    CP_COMMIT();
    if (nc > 2) issue_chunk(2, 2);
    CP_COMMIT();

    int cb = 0;   // buffer of chunk c
    for (int c = 0; c < nc; c++) {
        CP_WAIT(2);          // chunk c complete (c+1, c+2 may be in flight)
        __syncthreads();     // all warps done reading buf (cb+3)%4 (chunk c-1)
        if (c + 3 < nc) issue_chunk(c + 3, (cb + 3) & 3);
        CP_COMMIT();         // always commit (possibly empty) so counts work

        const uint32_t base = sb + (uint32_t)cb * STAGE_SZ;
        #pragma unroll
        for (int ks = 0; ks < 2; ks++) {
            uint32_t aR[4][4], bF[2][4];
            #pragma unroll
            for (int bg = 0; bg < 2; bg++) {
                const uint32_t bd = base + 10240 + (uint32_t)(wn + bg * 16) * RS + ks * 32 + b_lo;
                LDM4(bF[bg], bd);
            }
            #pragma unroll
            for (int mi = 0; mi < 4; mi++) {
                const uint32_t ad = base + (uint32_t)(wm + mi * 16) * RS + ks * 32 + a_lo;
                LDM4(aR[mi], ad);
            }
            #pragma unroll
            for (int mi = 0; mi < 4; mi++)
                #pragma unroll
                for (int nj = 0; nj < 4; nj++) {
                    const uint32_t* bf = &bF[nj >> 1][(nj & 1) * 2];
                    MMA16(acc[mi][nj], aR[mi], bf[0], bf[1]);
                }
        }
        cb = (cb + 1) & 3;
    }

    // ---- epilogue ----
    #pragma unroll
    for (int mi = 0; mi < 4; mi++) {
        #pragma unroll
        for (int h2 = 0; h2 < 2; h2++) {
            const int r = wm + mi * 16 + (lane >> 2) + h2 * 8;
            size_t orow;
            if (MODE == 2)
                orow = (size_t)((bB * 256 + gh0 + (r >> 4)) * 256 + gw0 + (r & 15));
            else
                orow = (size_t)(m0 + r);
            #pragma unroll
            for (int nj = 0; nj < 4; nj++) {
                const int n = n0 + wn + nj * 8 + (lane & 3) * 2;
                float v0 = acc[mi][nj][h2 * 2 + 0] + __ldg(&bias[n]);
                float v1 = acc[mi][nj][h2 * 2 + 1] + __ldg(&bias[n + 1]);
                if (EPI == 1) {
                    v0 = 0.5f * v0 * (1.0f + erff(v0 * 0.7071067811865476f));
                    v1 = 0.5f * v1 * (1.0f + erff(v1 * 0.7071067811865476f));
                }
                if (EPI == 3 || EPI == 4) {
                    v0 = v0 >= 0.f ? v0 : 0.01f * v0;
                    v1 = v1 >= 0.f ? v1 : 0.01f * v1;
                }
                if (EPI == 2) {
                    const float2 rv = *(const float2*)(res + orow * ldRes + n);
                    v0 += rv.x; v1 += rv.y;
                }
                if (EPI == 4) {
                    const float2 rv = *(const float2*)(res + orow * ldRes + n);
                    v0 += 2.f * rv.x; v1 += 2.f * rv.y;
                }
                if (WF)
                    *(float2*)(out + orow * ldo + n) = make_float2(v0, v1);
                if (WBF && n < ldob)
                    *(uint32_t*)(ob + orow * ldob + n) = pack_h2(v0, v1);
            }
        }
    }
}

// ---------------- LayerNorm (fp32 in, fp16 out) ----------------
__global__ void __launch_bounds__(256) ln_k(
    const float* __restrict__ in, int stride,
    const float* __restrict__ g, const float* __restrict__ bta,
    __half* __restrict__ o16)
{
    const int token = blockIdx.x * 8 + (threadIdx.x >> 5);
    const int lane = threadIdx.x & 31;
    const float* p = in + (size_t)token * stride;
    float4 v = *(const float4*)(p + lane * 4);
    float s  = v.x + v.y + v.z + v.w;
    float sq = v.x * v.x + v.y * v.y + v.z * v.z + v.w * v.w;
    #pragma unroll
    for (int o = 16; o; o >>= 1) {
        s  += __shfl_xor_sync(0xffffffffu, s,  o);
        sq += __shfl_xor_sync(0xffffffffu, sq, o);
    }
    const float mu  = s * (1.0f / 128.0f);
    const float var = sq * (1.0f / 128.0f) - mu * mu;
    const float rs  = rsqrtf(var + 1e-5f);
    float4 gv = *(const float4*)(g + lane * 4);
    float4 bv = *(const float4*)(bta + lane * 4);
    float o0 = (v.x - mu) * rs * gv.x + bv.x;
    float o1 = (v.y - mu) * rs * gv.y + bv.y;
    float o2 = (v.z - mu) * rs * gv.z + bv.z;
    float o3 = (v.w - mu) * rs * gv.w + bv.w;
    const size_t off = (size_t)token * 128 + lane * 4;
    *(uint2*)(o16 + off) = make_uint2(pack_h2(o0, o1), pack_h2(o2, o3));
}

// ---------------- windowed attention (fp32; fp16 out) ----------------
__global__ void __launch_bounds__(256) attn_k(
    const float* __restrict__ qkv, const float* __restrict__ rpb,
    __half* __restrict__ o16)
{
    __shared__ float qs[64][32];
    __shared__ float ks[64][33];
    __shared__ float vs[64][33];
    __shared__ float Ps[64][65];
    __shared__ int pixS[64];
    __shared__ int ridS[64];

    const int tid = threadIdx.x;
    const int head = blockIdx.x & 3;
    const int w = (blockIdx.x >> 2) & 1023;
    const int b = blockIdx.x >> 12;
    const int wi = w >> 5, wj = w & 31;

    if (tid < 64) {
        const int ti = tid >> 3, tj = tid & 7;
        const int hh = wi * 8 + ti, ww = wj * 8 + tj;
        pixS[tid] = (b * 256 + ((hh + 4) & 255)) * 256 + ((ww + 4) & 255);
        const int rh = hh < 248 ? 0 : (hh < 252 ? 1 : 2);
        const int rw = ww < 248 ? 0 : (ww < 252 ? 1 : 2);
        ridS[tid] = rh * 3 + rw;
    }
    __syncthreads();

    const int ho = head * 32;
    for (int idx = tid; idx < 2048; idx += 256) {
        const int t = idx >> 5, d = idx & 31;
        const size_t base = (size_t)pixS[t] * 384 + ho + d;
        qs[t][d] = qkv[base];
        ks[t][d] = qkv[base + 128];
        vs[t][d] = qkv[base + 256];
    }
    __syncthreads();

    const int warp = tid >> 5, lane = tid & 31;
    #pragma unroll
    for (int rr = 0; rr < 8; rr++) {
        const int r = warp * 8 + rr;
        float s0 = 0.f, s1 = 0.f;
        #pragma unroll
        for (int d = 0; d < 32; d++) {
            const float qv = qs[r][d];
            s0 += qv * ks[lane][d];
            s1 += qv * ks[lane + 32][d];
        }
        const int ri = r >> 3, rj = r & 7;
        const int rid_r = ridS[r];
        {
            const int c = lane;
            const int rel = (ri - (c >> 3) + 7) * 15 + (rj - (c & 7) + 7);
            s0 = s0 * 0.17677669529663687f + rpb[rel * 4 + head];
            if (rid_r != ridS[c]) s0 -= 1e9f;
        }
        {
            const int c = lane + 32;
            const int rel = (ri - (c >> 3) + 7) * 15 + (rj - (c & 7) + 7);
            s1 = s1 * 0.17677669529663687f + rpb[rel * 4 + head];
            if (rid_r != ridS[c]) s1 -= 1e9f;
        }
        float mx = fmaxf(s0, s1);
        #pragma unroll
        for (int o = 16; o; o >>= 1) mx = fmaxf(mx, __shfl_xor_sync(0xffffffffu, mx, o));
        float e0 = expf(s0 - mx), e1 = expf(s1 - mx);
        float sm = e0 + e1;
        #pragma unroll
        for (int o = 16; o; o >>= 1) sm += __shfl_xor_sync(0xffffffffu, sm, o);
        const float inv = 1.0f / sm;
        Ps[r][lane] = e0 * inv;
        Ps[r][lane + 32] = e1 * inv;
    }
    __syncthreads();

    const int i = tid >> 2, d0 = (tid & 3) * 8;
    float acc[8] = {};
    #pragma unroll
    for (int j = 0; j < 64; j++) {
        const float p = Ps[i][j];
        #pragma unroll
        for (int dd = 0; dd < 8; dd++) acc[dd] += p * vs[j][d0 + dd];
    }
    const size_t ob = (size_t)pixS[i] * 128 + ho + d0;
    #pragma unroll
    for (int dd = 0; dd < 8; dd += 2)
        *(uint32_t*)(o16 + ob + dd) = pack_h2(acc[dd], acc[dd + 1]);
}

// ===========================================================================
extern "C" void kernel_launch(void* const* d_in, const int* in_sizes, int n_in,
                              void* d_out, int out_size)
{
    const float* x    = (const float*)d_in[0];
    const float* c1w  = (const float*)d_in[1];
    const float* c1b  = (const float*)d_in[2];
    const float* rw1  = (const float*)d_in[3];
    const float* rb1  = (const float*)d_in[4];
    const float* rw2  = (const float*)d_in[5];
    const float* rb2  = (const float*)d_in[6];
    const float* ln1g = (const float*)d_in[7];
    const float* ln1b = (const float*)d_in[8];
    const float* qkvw = (const float*)d_in[9];
    const float* qkvb = (const float*)d_in[10];
    const float* rpb  = (const float*)d_in[11];
    const float* pw   = (const float*)d_in[12];
    const float* pb   = (const float*)d_in[13];
    const float* ln2g = (const float*)d_in[14];
    const float* ln2b = (const float*)d_in[15];
    const float* mw1  = (const float*)d_in[16];
    const float* mb1  = (const float*)d_in[17];
    const float* mw2  = (const float*)d_in[18];
    const float* mb2  = (const float*)d_in[19];
    const float* c2w  = (const float*)d_in[20];
    const float* c2b  = (const float*)d_in[21];
    float* out = (float*)d_out;

    float *y, *qkv, *t;
    __half *x16,*y16,*r16,*c16,*l16,*a16,*u16,*t16,*wt;
    cudaGetSymbolAddress((void**)&y,   g_y);
    cudaGetSymbolAddress((void**)&qkv, g_qkv);
    cudaGetSymbolAddress((void**)&t,   g_t);
    cudaGetSymbolAddress((void**)&x16, g_x16);
    cudaGetSymbolAddress((void**)&y16, g_y16);
    cudaGetSymbolAddress((void**)&r16, g_r16);
    cudaGetSymbolAddress((void**)&c16, g_c16);
    cudaGetSymbolAddress((void**)&l16, g_l16);
    cudaGetSymbolAddress((void**)&a16, g_a16);
    cudaGetSymbolAddress((void**)&u16, g_u16);
    cudaGetSymbolAddress((void**)&t16, g_t16);
    cudaGetSymbolAddress((void**)&wt,  g_wt);

    // one-time objects (same work every call; creation only happens once,
    // before the first graph capture)
    static cudaStream_t s2 = nullptr;
    static cudaEvent_t evFork = nullptr, evJoin = nullptr;
    if (s2 == nullptr) {
        cudaStreamCreateWithFlags(&s2, cudaStreamNonBlocking);
        cudaEventCreateWithFlags(&evFork, cudaEventDisableTiming);
        cudaEventCreateWithFlags(&evJoin, cudaEventDisableTiming);
        cudaFuncSetAttribute(mm_k<0,0,1,1>, cudaFuncAttributeMaxDynamicSharedMemorySize, SMEM_TOTAL);
        cudaFuncSetAttribute(mm_k<2,3,0,1>, cudaFuncAttributeMaxDynamicSharedMemorySize, SMEM_TOTAL);
        cudaFuncSetAttribute(mm_k<2,4,0,1>, cudaFuncAttributeMaxDynamicSharedMemorySize, SMEM_TOTAL);
        cudaFuncSetAttribute(mm_k<0,0,1,0>, cudaFuncAttributeMaxDynamicSharedMemorySize, SMEM_TOTAL);
        cudaFuncSetAttribute(mm_k<0,2,1,0>, cudaFuncAttributeMaxDynamicSharedMemorySize, SMEM_TOTAL);
        cudaFuncSetAttribute(mm_k<0,1,0,1>, cudaFuncAttributeMaxDynamicSharedMemorySize, SMEM_TOTAL);
        cudaFuncSetAttribute(mm_k<0,2,0,1>, cudaFuncAttributeMaxDynamicSharedMemorySize, SMEM_TOTAL);
        cudaFuncSetAttribute(mm_k<1,2,1,0>, cudaFuncAttributeMaxDynamicSharedMemorySize, SMEM_TOTAL);
    }

    // 0a. weight prep
    PrepArgs pa;
    pa.src[0]=c1w; pa.K[0]=256;  pa.N[0]=256; pa.off[0]=OFF_C1;
    pa.src[1]=rw1; pa.K[1]=1152; pa.N[1]=128; pa.off[1]=OFF_RW1;
    pa.src[2]=rw2; pa.K[2]=1152; pa.N[2]=128; pa.off[2]=OFF_RW2;
    pa.src[3]=qkvw;pa.K[3]=128;  pa.N[3]=384; pa.off[3]=OFF_QKV;
    pa.src[4]=pw;  pa.K[4]=128;  pa.N[4]=128; pa.off[4]=OFF_PW;
    pa.src[5]=mw1; pa.K[5]=128;  pa.N[5]=512; pa.off[5]=OFF_MW1;
    pa.src[6]=mw2; pa.K[6]=512;  pa.N[6]=128; pa.off[6]=OFF_MW2;
    pa.src[7]=c2w; pa.K[7]=256;  pa.N[7]=256; pa.off[7]=OFF_C2;
    prep_k<<<dim3(576, 8), 256>>>(pa, wt);
    // 0b. convert x
    cvt_k<<<32768, 256>>>(x, x16, M_TOK * 64);

    const int M = M_TOK;
    // 1. conv1x1 #1: y(fp32 [M,256]) + y16(cols 0-127)
    mm_k<0,0,1,1><<<dim3(M/128, 2), 256, SMEM_TOTAL>>>(
        x16, nullptr, 256, wt+OFF_C1, 256,
        c1b, nullptr, 0, y, 256, y16, 128);

    // ---- fork: conv branch on s2, transformer branch on capture stream ----
    cudaEventRecord(evFork, 0);
    cudaStreamWaitEvent(s2, evFork, 0);

    // conv branch (s2)
    // 2. conv3x3 #1 + lrelu -> r16
    mm_k<2,3,0,1><<<1024, 256, SMEM_TOTAL, s2>>>(
        y16, nullptr, 128, wt+OFF_RW1, 1152,
        rb1, nullptr, 0, nullptr, 0, r16, 128);
    // 3. conv3x3 #2 + lrelu + 2*conv_x -> c16
    mm_k<2,4,0,1><<<1024, 256, SMEM_TOTAL, s2>>>(
        r16, nullptr, 128, wt+OFF_RW2, 1152,
        rb2, y, 256, nullptr, 0, c16, 128);

    // transformer branch (capture stream)
    // 4. LN1 on trans_x -> l16
    ln_k<<<M/8, 256>>>(y + 128, 256, ln1g, ln1b, l16);
    // 5. qkv (fp32)
    mm_k<0,0,1,0><<<dim3(M/128, 3), 256, SMEM_TOTAL>>>(
        l16, nullptr, 128, wt+OFF_QKV, 128,
        qkvb, nullptr, 0, qkv, 384, nullptr, 0);
    // 6. attention -> a16
    attn_k<<<8192, 256>>>(qkv, rpb, a16);
    // 7. proj + residual(trans_x) -> t (fp32)
    mm_k<0,2,1,0><<<dim3(M/128, 1), 256, SMEM_TOTAL>>>(
        a16, nullptr, 128, wt+OFF_PW, 128,
        pb, y + 128, 256, t, 128, nullptr, 0);
    // 8. LN2 -> l16
    ln_k<<<M/8, 256>>>(t, 128, ln2g, ln2b, l16);
    // 9. mlp1 + gelu -> u16
    mm_k<0,1,0,1><<<dim3(M/128, 4), 256, SMEM_TOTAL>>>(
        l16, nullptr, 128, wt+OFF_MW1, 128,
        mb1, nullptr, 0, nullptr, 0, u16, 512);
    // 10. mlp2 + residual(t) -> t16
    mm_k<0,2,0,1><<<dim3(M/128, 1), 256, SMEM_TOTAL>>>(
        u16, nullptr, 512, wt+OFF_MW2, 512,
        mb2, t, 128, nullptr, 0, t16, 128);

    // ---- join ----
    cudaEventRecord(evJoin, s2);
    cudaStreamWaitEvent(0, evJoin, 0);

    // 11. conv1x1 #2 on concat(c16,t16) + x -> out
    mm_k<1,2,1,0><<<dim3(M/128, 2), 256, SMEM_TOTAL>>>(
        c16, t16, 0, wt+OFF_C2, 256,
        c2b, x, 256, out, 256, nullptr, 0);
}

// round 12
// speedup vs baseline: 1.7638x; 1.0046x over previous
#include <cuda_runtime.h>
#include <cuda_fp16.h>
#include <math.h>
#include <stdint.h>

// ===========================================================================
// ConvTransBlock via legacy tensor-core path (mma.sync fp16 single-product).
// B=2, H=W=256, C=256 (CD=128 | TD=128), WS=8, NH=4, HD=32.
// R10: R8 tile shape (128x128, 256thr, 2 CTA/SM) + fp16 1-product GEMMs
//      (3x fewer MMAs) + 4-stage cp.async pipeline.
// ===========================================================================

#define M_TOK 131072

// ---------------- fp32 buffers ----------------
__device__ float g_y  [131072 * 256];   // conv1 out
__device__ float g_qkv[131072 * 384];
__device__ float g_t  [131072 * 128];   // trans after proj residual

// ---------------- fp16 activation buffers ----------------
__device__ __half g_x16[131072*256];
__device__ __half g_y16[131072*128];   // conv half of y
__device__ __half g_r16[131072*128];
__device__ __half g_c16[131072*128];   // cx
__device__ __half g_l16[131072*128];   // ln out
__device__ __half g_a16[131072*128];   // attn out
__device__ __half g_u16[131072*512];   // mlp hidden
__device__ __half g_t16[131072*128];   // t2

// transposed fp16 weights, K-major rows per n
#define WT_TOTAL 622592
__device__ __align__(256) __half g_wt[WT_TOTAL];
#define OFF_C1   0
#define OFF_RW1  65536
#define OFF_RW2  212992
#define OFF_QKV  360448
#define OFF_PW   409600
#define OFF_MW1  425984
#define OFF_MW2  491520
#define OFF_C2   557056

// ---------------- PTX helpers (all sm_80-compatible) ----------------
__device__ __forceinline__ uint32_t smem_u32(const void* p) {
    uint32_t a;
    asm("{ .reg .u64 t; cvta.to.shared.u64 t, %1; cvt.u32.u64 %0, t; }" : "=r"(a) : "l"(p));
    return a;
}
#define CP_ASYNC(dst, src, sz) \
    asm volatile("cp.async.cg.shared.global [%0], [%1], 16, %2;" \
        :: "r"(dst), "l"(src), "r"(sz))
#define CP_COMMIT() asm volatile("cp.async.commit_group;")
#define CP_WAIT(n)  asm volatile("cp.async.wait_group %0;" :: "n"(n))
#define LDM4(r, addr) \
    asm volatile("ldmatrix.sync.aligned.m8n8.x4.shared.b16 {%0,%1,%2,%3}, [%4];" \
        : "=r"((r)[0]), "=r"((r)[1]), "=r"((r)[2]), "=r"((r)[3]) : "r"(addr))
#define MMA16(d, a, b0, b1) \
    asm volatile("mma.sync.aligned.m16n8k16.row.col.f32.f16.f16.f32 " \
        "{%0,%1,%2,%3}, {%4,%5,%6,%7}, {%8,%9}, {%0,%1,%2,%3};" \
        : "+f"((d)[0]), "+f"((d)[1]), "+f"((d)[2]), "+f"((d)[3]) \
        : "r"((a)[0]), "r"((a)[1]), "r"((a)[2]), "r"((a)[3]), "r"(b0), "r"(b1))

__device__ __forceinline__ uint32_t pack_h2(float a, float b) {
    __half ha = __float2half_rn(a), hb = __float2half_rn(b);
    return ((uint32_t)__half_as_ushort(hb) << 16) | (uint32_t)__half_as_ushort(ha);
}

// ---------------- weight prep: W[k][n] -> Wt[n][k] fp16 ----------------
struct PrepArgs { const float* src[8]; int K[8], N[8], off[8]; };
__global__ void __launch_bounds__(256) prep_k(PrepArgs a, __half* __restrict__ d)
{
    int w = blockIdx.y;
    int K = a.K[w], N = a.N[w];
    int idx = blockIdx.x * 256 + threadIdx.x;
    if (idx >= K * N) return;
    int n = idx / K, k = idx - n * K;
    d[a.off[w] + idx] = __float2half_rn(a.src[w][(size_t)k * N + n]);
}

// ---------------- fp32 -> fp16 converter (for x) ----------------
__global__ void __launch_bounds__(256) cvt_k(const float* __restrict__ in,
    __half* __restrict__ o16, int n4)
{
    int i = blockIdx.x * 256 + threadIdx.x;
    if (i >= n4) return;
    float4 v = ((const float4*)in)[i];
    ((uint2*)o16)[i] = make_uint2(pack_h2(v.x, v.y), pack_h2(v.z, v.w));
}

// ---------------- unified tensor-core GEMM / implicit-GEMM conv ----------------
// Block tile 128x128, 256 threads (8 warps, warp = m64 x n32), 2 CTAs/SM.
// MODE: 0 gemm, 1 concat(A0,A1) along K, 2 conv3x3 (A = [M,128] fp16, halo)
// EPI:  0 bias; 1 bias+gelu; 2 bias+res; 3 bias+lrelu; 4 bias+lrelu+2*res
// WF:   write fp32 out;  WBF: write fp16 out (cols < ldob)
#define RS 80                       // smem row stride bytes (32 fp16 + pad)
#define STAGE_SZ 20480              // A@0 (128*80) | B@10240 (128*80)
#define NSTAGE 4
#define SMEM_TOTAL (NSTAGE * STAGE_SZ)   // 81920 B/CTA, 2 CTAs = 160 KB/SM

template<int MODE, int EPI, int WF, int WBF>
__global__ void __launch_bounds__(256, 2) mm_k(
    const __half* __restrict__ A0, const __half* __restrict__ A1, int ldA,
    const __half* __restrict__ WH, int Kw,
    const float* __restrict__ bias,
    const float* __restrict__ res, int ldRes,
    float* __restrict__ out, int ldo,
    __half* __restrict__ ob, int ldob)
{
    extern __shared__ char sm[];
    const uint32_t sb = smem_u32(sm);
    const int tid = threadIdx.x;
    const int wid = tid >> 5;
    const int lane = tid & 31;
    const int nc = Kw >> 5;

    int m0 = 0, n0 = 0, bB = 0, gh0 = 0, gw0 = 0;
    if (MODE == 2) {
        bB  = blockIdx.x >> 9;
        gh0 = ((blockIdx.x >> 4) & 31) * 8;
        gw0 = (blockIdx.x & 15) * 16;
    } else {
        m0 = blockIdx.x * 128;
        n0 = blockIdx.y * 128;
    }

    // loader mapping: 2 threads per row, each covers a 32B k-half (2x16B)
    const int lr = tid >> 1;
    const int lh = tid & 1;
    int lph = 0, lpw = 0;
    if (MODE == 2) { lph = gh0 + (lr >> 4); lpw = gw0 + (lr & 15); }

    auto issue_chunk = [&](int cc, int buf) {
        const uint32_t base = sb + (uint32_t)buf * STAGE_SZ;
        const int kin = cc * 32;
        // ---- A ----
        const __half* ah;
        uint32_t asz = 16;
        if (MODE == 0) {
            ah = A0 + (size_t)(m0 + lr) * ldA + kin;
        } else if (MODE == 1) {
            ah = (kin < 128) ? A0 + (size_t)(m0 + lr) * 128 + kin
                             : A1 + (size_t)(m0 + lr) * 128 + (kin - 128);
        } else {
            const int tap = cc >> 2, kk = (cc & 3) * 32;
            const int ih = lph + tap / 3 - 1, iw = lpw + tap % 3 - 1;
            const bool ok = ((unsigned)ih < 256u) && ((unsigned)iw < 256u);
            const size_t pix = ok ? (size_t)((bB * 256 + ih) * 256 + iw) : 0;
            ah = A0 + pix * 128 + kk;
            asz = ok ? 16u : 0u;
        }
        const uint32_t da = base + (uint32_t)lr * RS + lh * 32;
        CP_ASYNC(da,      (const char*)ah + lh * 32,      asz);
        CP_ASYNC(da + 16, (const char*)ah + lh * 32 + 16, asz);
        // ---- B (weights, K-major rows) ----
        const __half* bh = WH + (size_t)(n0 + lr) * Kw + kin;
        const uint32_t db = base + 10240 + (uint32_t)lr * RS + lh * 32;
        CP_ASYNC(db,      (const char*)bh + lh * 32,      16);
        CP_ASYNC(db + 16, (const char*)bh + lh * 32 + 16, 16);
    };

    // warp tiling: warp_m in {0,1} (64 rows), warp_n in {0..3} (32 cols)
    const int wm = (wid & 1) * 64;
    const int wn = (wid >> 1) * 32;
    const uint32_t a_lo = (uint32_t)(lane & 15) * RS + (uint32_t)(lane >> 4) * 16;
    const uint32_t b_lo = (uint32_t)((lane & 7) + ((lane >> 4) << 3)) * RS
                        + (uint32_t)((lane >> 3) & 1) * 16;

    float acc[4][4][4] = {};

    // 4-stage pipeline: 3 chunks in flight, wait_group 2
    issue_chunk(0, 0); CP_COMMIT();
    if (nc > 1) issue_chunk(1, 1);
    CP_COMMIT();
    if (nc > 2) issue_chunk(2, 2);
    CP_COMMIT();

    int cb = 0;   // buffer of chunk c
    for (int c = 0; c < nc; c++) {
        CP_WAIT(2);          // chunk c complete (c+1, c+2 may be in flight)
        __syncthreads();     // all warps done reading buf (cb+3)%4 (chunk c-1)
        if (c + 3 < nc) issue_chunk(c + 3, (cb + 3) & 3);
        CP_COMMIT();         // always commit (possibly empty) so counts work

        const uint32_t base = sb + (uint32_t)cb * STAGE_SZ;
        #pragma unroll
        for (int ks = 0; ks < 2; ks++) {
            uint32_t aR[4][4], bF[2][4];
            #pragma unroll
            for (int bg = 0; bg < 2; bg++) {
                const uint32_t bd = base + 10240 + (uint32_t)(wn + bg * 16) * RS + ks * 32 + b_lo;
                LDM4(bF[bg], bd);
            }
            #pragma unroll
            for (int mi = 0; mi < 4; mi++) {
                const uint32_t ad = base + (uint32_t)(wm + mi * 16) * RS + ks * 32 + a_lo;
                LDM4(aR[mi], ad);
            }
            #pragma unroll
            for (int mi = 0; mi < 4; mi++)
                #pragma unroll
                for (int nj = 0; nj < 4; nj++) {
                    const uint32_t* bf = &bF[nj >> 1][(nj & 1) * 2];
                    MMA16(acc[mi][nj], aR[mi], bf[0], bf[1]);
                }
        }
        cb = (cb + 1) & 3;
    }

    // ---- epilogue ----
    #pragma unroll
    for (int mi = 0; mi < 4; mi++) {
        #pragma unroll
        for (int h2 = 0; h2 < 2; h2++) {
            const int r = wm + mi * 16 + (lane >> 2) + h2 * 8;
            size_t orow;
            if (MODE == 2)
                orow = (size_t)((bB * 256 + gh0 + (r >> 4)) * 256 + gw0 + (r & 15));
            else
                orow = (size_t)(m0 + r);
            #pragma unroll
            for (int nj = 0; nj < 4; nj++) {
                const int n = n0 + wn + nj * 8 + (lane & 3) * 2;
                float v0 = acc[mi][nj][h2 * 2 + 0] + __ldg(&bias[n]);
                float v1 = acc[mi][nj][h2 * 2 + 1] + __ldg(&bias[n + 1]);
                if (EPI == 1) {
                    v0 = 0.5f * v0 * (1.0f + erff(v0 * 0.7071067811865476f));
                    v1 = 0.5f * v1 * (1.0f + erff(v1 * 0.7071067811865476f));
                }
                if (EPI == 3 || EPI == 4) {
                    v0 = v0 >= 0.f ? v0 : 0.01f * v0;
                    v1 = v1 >= 0.f ? v1 : 0.01f * v1;
                }
                if (EPI == 2) {
                    const float2 rv = *(const float2*)(res + orow * ldRes + n);
                    v0 += rv.x; v1 += rv.y;
                }
                if (EPI == 4) {
                    const float2 rv = *(const float2*)(res + orow * ldRes + n);
                    v0 += 2.f * rv.x; v1 += 2.f * rv.y;
                }
                if (WF)
                    *(float2*)(out + orow * ldo + n) = make_float2(v0, v1);
                if (WBF && n < ldob)
                    *(uint32_t*)(ob + orow * ldob + n) = pack_h2(v0, v1);
            }
        }
    }
}

// ---------------- LayerNorm (fp32 in, fp16 out) ----------------
__global__ void __launch_bounds__(256) ln_k(
    const float* __restrict__ in, int stride,
    const float* __restrict__ g, const float* __restrict__ bta,
    __half* __restrict__ o16)
{
    const int token = blockIdx.x * 8 + (threadIdx.x >> 5);
    const int lane = threadIdx.x & 31;
    const float* p = in + (size_t)token * stride;
    float4 v = *(const float4*)(p + lane * 4);
    float s  = v.x + v.y + v.z + v.w;
    float sq = v.x * v.x + v.y * v.y + v.z * v.z + v.w * v.w;
    #pragma unroll
    for (int o = 16; o; o >>= 1) {
        s  += __shfl_xor_sync(0xffffffffu, s,  o);
        sq += __shfl_xor_sync(0xffffffffu, sq, o);
    }
    const float mu  = s * (1.0f / 128.0f);
    const float var = sq * (1.0f / 128.0f) - mu * mu;
    const float rs  = rsqrtf(var + 1e-5f);
    float4 gv = *(const float4*)(g + lane * 4);
    float4 bv = *(const float4*)(bta + lane * 4);
    float o0 = (v.x - mu) * rs * gv.x + bv.x;
    float o1 = (v.y - mu) * rs * gv.y + bv.y;
    float o2 = (v.z - mu) * rs * gv.z + bv.z;
    float o3 = (v.w - mu) * rs * gv.w + bv.w;
    const size_t off = (size_t)token * 128 + lane * 4;
    *(uint2*)(o16 + off) = make_uint2(pack_h2(o0, o1), pack_h2(o2, o3));
}

// ---------------- windowed attention (fp32; fp16 out) ----------------
__global__ void __launch_bounds__(256) attn_k(
    const float* __restrict__ qkv, const float* __restrict__ rpb,
    __half* __restrict__ o16)
{
    __shared__ float qs[64][32];
    __shared__ float ks[64][33];
    __shared__ float vs[64][33];
    __shared__ float Ps[64][65];
    __shared__ int pixS[64];
    __shared__ int ridS[64];

    const int tid = threadIdx.x;
    const int head = blockIdx.x & 3;
    const int w = (blockIdx.x >> 2) & 1023;
    const int b = blockIdx.x >> 12;
    const int wi = w >> 5, wj = w & 31;

    if (tid < 64) {
        const int ti = tid >> 3, tj = tid & 7;
        const int hh = wi * 8 + ti, ww = wj * 8 + tj;
        pixS[tid] = (b * 256 + ((hh + 4) & 255)) * 256 + ((ww + 4) & 255);
        const int rh = hh < 248 ? 0 : (hh < 252 ? 1 : 2);
        const int rw = ww < 248 ? 0 : (ww < 252 ? 1 : 2);
        ridS[tid] = rh * 3 + rw;
    }
    __syncthreads();

    const int ho = head * 32;
    for (int idx = tid; idx < 2048; idx += 256) {
        const int t = idx >> 5, d = idx & 31;
        const size_t base = (size_t)pixS[t] * 384 + ho + d;
        qs[t][d] = qkv[base];
        ks[t][d] = qkv[base + 128];
        vs[t][d] = qkv[base + 256];
    }
    __syncthreads();

    const int warp = tid >> 5, lane = tid & 31;
    #pragma unroll
    for (int rr = 0; rr < 8; rr++) {
        const int r = warp * 8 + rr;
        float s0 = 0.f, s1 = 0.f;
        #pragma unroll
        for (int d = 0; d < 32; d++) {
            const float qv = qs[r][d];
            s0 += qv * ks[lane][d];
            s1 += qv * ks[lane + 32][d];
        }
        const int ri = r >> 3, rj = r & 7;
        const int rid_r = ridS[r];
        {
            const int c = lane;
            const int rel = (ri - (c >> 3) + 7) * 15 + (rj - (c & 7) + 7);
            s0 = s0 * 0.17677669529663687f + rpb[rel * 4 + head];
            if (rid_r != ridS[c]) s0 -= 1e9f;
        }
        {
            const int c = lane + 32;
            const int rel = (ri - (c >> 3) + 7) * 15 + (rj - (c & 7) + 7);
            s1 = s1 * 0.17677669529663687f + rpb[rel * 4 + head];
            if (rid_r != ridS[c]) s1 -= 1e9f;
        }
        float mx = fmaxf(s0, s1);
        #pragma unroll
        for (int o = 16; o; o >>= 1) mx = fmaxf(mx, __shfl_xor_sync(0xffffffffu, mx, o));
        float e0 = expf(s0 - mx), e1 = expf(s1 - mx);
        float sm = e0 + e1;
        #pragma unroll
        for (int o = 16; o; o >>= 1) sm += __shfl_xor_sync(0xffffffffu, sm, o);
        const float inv = 1.0f / sm;
        Ps[r][lane] = e0 * inv;
        Ps[r][lane + 32] = e1 * inv;
    }
    __syncthreads();

    const int i = tid >> 2, d0 = (tid & 3) * 8;
    float acc[8] = {};
    #pragma unroll
    for (int j = 0; j < 64; j++) {
        const float p = Ps[i][j];
        #pragma unroll
        for (int dd = 0; dd < 8; dd++) acc[dd] += p * vs[j][d0 + dd];
    }
    const size_t ob = (size_t)pixS[i] * 128 + ho + d0;
    #pragma unroll
    for (int dd = 0; dd < 8; dd += 2)
        *(uint32_t*)(o16 + ob + dd) = pack_h2(acc[dd], acc[dd + 1]);
}

// ===========================================================================
extern "C" void kernel_launch(void* const* d_in, const int* in_sizes, int n_in,
                              void* d_out, int out_size)
{
    const float* x    = (const float*)d_in[0];
    const float* c1w  = (const float*)d_in[1];
    const float* c1b  = (const float*)d_in[2];
    const float* rw1  = (const float*)d_in[3];
    const float* rb1  = (const float*)d_in[4];
    const float* rw2  = (const float*)d_in[5];
    const float* rb2  = (const float*)d_in[6];
    const float* ln1g = (const float*)d_in[7];
    const float* ln1b = (const float*)d_in[8];
    const float* qkvw = (const float*)d_in[9];
    const float* qkvb = (const float*)d_in[10];
    const float* rpb  = (const float*)d_in[11];
    const float* pw   = (const float*)d_in[12];
    const float* pb   = (const float*)d_in[13];
    const float* ln2g = (const float*)d_in[14];
    const float* ln2b = (const float*)d_in[15];
    const float* mw1  = (const float*)d_in[16];
    const float* mb1  = (const float*)d_in[17];
    const float* mw2  = (const float*)d_in[18];
    const float* mb2  = (const float*)d_in[19];
    const float* c2w  = (const float*)d_in[20];
    const float* c2b  = (const float*)d_in[21];
    float* out = (float*)d_out;

    float *y, *qkv, *t;
    __half *x16,*y16,*r16,*c16,*l16,*a16,*u16,*t16,*wt;
    cudaGetSymbolAddress((void**)&y,   g_y);
    cudaGetSymbolAddress((void**)&qkv, g_qkv);
    cudaGetSymbolAddress((void**)&t,   g_t);
    cudaGetSymbolAddress((void**)&x16, g_x16);
    cudaGetSymbolAddress((void**)&y16, g_y16);
    cudaGetSymbolAddress((void**)&r16, g_r16);
    cudaGetSymbolAddress((void**)&c16, g_c16);
    cudaGetSymbolAddress((void**)&l16, g_l16);
    cudaGetSymbolAddress((void**)&a16, g_a16);
    cudaGetSymbolAddress((void**)&u16, g_u16);
    cudaGetSymbolAddress((void**)&t16, g_t16);
    cudaGetSymbolAddress((void**)&wt,  g_wt);

    // one-time objects (same work every call; creation only happens once,
    // before the first graph capture)
    static cudaStream_t s2 = nullptr;
    static cudaEvent_t evFork = nullptr, evJoin = nullptr;
    if (s2 == nullptr) {
        cudaStreamCreateWithFlags(&s2, cudaStreamNonBlocking);
        cudaEventCreateWithFlags(&evFork, cudaEventDisableTiming);
        cudaEventCreateWithFlags(&evJoin, cudaEventDisableTiming);
        cudaFuncSetAttribute(mm_k<0,0,1,1>, cudaFuncAttributeMaxDynamicSharedMemorySize, SMEM_TOTAL);
        cudaFuncSetAttribute(mm_k<2,3,0,1>, cudaFuncAttributeMaxDynamicSharedMemorySize, SMEM_TOTAL);
        cudaFuncSetAttribute(mm_k<2,4,0,1>, cudaFuncAttributeMaxDynamicSharedMemorySize, SMEM_TOTAL);
        cudaFuncSetAttribute(mm_k<0,0,1,0>, cudaFuncAttributeMaxDynamicSharedMemorySize, SMEM_TOTAL);
        cudaFuncSetAttribute(mm_k<0,2,1,0>, cudaFuncAttributeMaxDynamicSharedMemorySize, SMEM_TOTAL);
        cudaFuncSetAttribute(mm_k<0,1,0,1>, cudaFuncAttributeMaxDynamicSharedMemorySize, SMEM_TOTAL);
        cudaFuncSetAttribute(mm_k<0,2,0,1>, cudaFuncAttributeMaxDynamicSharedMemorySize, SMEM_TOTAL);
        cudaFuncSetAttribute(mm_k<1,2,1,0>, cudaFuncAttributeMaxDynamicSharedMemorySize, SMEM_TOTAL);
    }

    // 0a. weight prep
    PrepArgs pa;
    pa.src[0]=c1w; pa.K[0]=256;  pa.N[0]=256; pa.off[0]=OFF_C1;
    pa.src[1]=rw1; pa.K[1]=1152; pa.N[1]=128; pa.off[1]=OFF_RW1;
    pa.src[2]=rw2; pa.K[2]=1152; pa.N[2]=128; pa.off[2]=OFF_RW2;
    pa.src[3]=qkvw;pa.K[3]=128;  pa.N[3]=384; pa.off[3]=OFF_QKV;
    pa.src[4]=pw;  pa.K[4]=128;  pa.N[4]=128; pa.off[4]=OFF_PW;
    pa.src[5]=mw1; pa.K[5]=128;  pa.N[5]=512; pa.off[5]=OFF_MW1;
    pa.src[6]=mw2; pa.K[6]=512;  pa.N[6]=128; pa.off[6]=OFF_MW2;
    pa.src[7]=c2w; pa.K[7]=256;  pa.N[7]=256; pa.off[7]=OFF_C2;
    prep_k<<<dim3(576, 8), 256>>>(pa, wt);
    // 0b. convert x
    cvt_k<<<32768, 256>>>(x, x16, M_TOK * 64);

    const int M = M_TOK;
    // 1. conv1x1 #1: y(fp32 [M,256]) + y16(cols 0-127)
    mm_k<0,0,1,1><<<dim3(M/128, 2), 256, SMEM_TOTAL>>>(
        x16, nullptr, 256, wt+OFF_C1, 256,
        c1b, nullptr, 0, y, 256, y16, 128);

    // ---- fork: conv branch on s2, transformer branch on capture stream ----
    cudaEventRecord(evFork, 0);
    cudaStreamWaitEvent(s2, evFork, 0);

    // conv branch (s2)
    // 2. conv3x3 #1 + lrelu -> r16
    mm_k<2,3,0,1><<<1024, 256, SMEM_TOTAL, s2>>>(
        y16, nullptr, 128, wt+OFF_RW1, 1152,
        rb1, nullptr, 0, nullptr, 0, r16, 128);
    // 3. conv3x3 #2 + lrelu + 2*conv_x -> c16
    mm_k<2,4,0,1><<<1024, 256, SMEM_TOTAL, s2>>>(
        r16, nullptr, 128, wt+OFF_RW2, 1152,
        rb2, y, 256, nullptr, 0, c16, 128);

    // transformer branch (capture stream)
    // 4. LN1 on trans_x -> l16
    ln_k<<<M/8, 256>>>(y + 128, 256, ln1g, ln1b, l16);
    // 5. qkv (fp32)
    mm_k<0,0,1,0><<<dim3(M/128, 3), 256, SMEM_TOTAL>>>(
        l16, nullptr, 128, wt+OFF_QKV, 128,
        qkvb, nullptr, 0, qkv, 384, nullptr, 0);
    // 6. attention -> a16
    attn_k<<<8192, 256>>>(qkv, rpb, a16);
    // 7. proj + residual(trans_x) -> t (fp32)
    mm_k<0,2,1,0><<<dim3(M/128, 1), 256, SMEM_TOTAL>>>(
        a16, nullptr, 128, wt+OFF_PW, 128,
        pb, y + 128, 256, t, 128, nullptr, 0);
    // 8. LN2 -> l16
    ln_k<<<M/8, 256>>>(t, 128, ln2g, ln2b, l16);
    // 9. mlp1 + gelu -> u16
    mm_k<0,1,0,1><<<dim3(M/128, 4), 256, SMEM_TOTAL>>>(
        l16, nullptr, 128, wt+OFF_MW1, 128,
        mb1, nullptr, 0, nullptr, 0, u16, 512);
    // 10. mlp2 + residual(t) -> t16
    mm_k<0,2,0,1><<<dim3(M/128, 1), 256, SMEM_TOTAL>>>(
        u16, nullptr, 512, wt+OFF_MW2, 512,
        mb2, t, 128, nullptr, 0, t16, 128);

    // ---- join ----
    cudaEventRecord(evJoin, s2);
    cudaStreamWaitEvent(0, evJoin, 0);

    // 11. conv1x1 #2 on concat(c16,t16) + x -> out
    mm_k<1,2,1,0><<<dim3(M/128, 2), 256, SMEM_TOTAL>>>(
        c16, t16, 0, wt+OFF_C2, 256,
        c2b, x, 256, out, 256, nullptr, 0);
}